// round 2
// baseline (speedup 1.0000x reference)
#include <cuda_runtime.h>
#include <cstdint>

// ---------------------------------------------------------------------------
// out[b,i,j] = sum_d relu(a[b,i,d] + c[b,j,d]) * W2[d] + b2
//   a = emb @ W1[:768] + b1,  c = emb @ W1[768:]
// emb (4,512,768) f32, W1 (1536,256), b1 (256), W2 (256,1), b2 (1)
// out (4,512,512) f32
// ---------------------------------------------------------------------------

#define B_   4
#define N_   512
#define H_   768
#define HID_ 256
#define M_   (B_ * N_)        // 2048

// Scratch, stored D-MAJOR: g_a[d * M_ + m]  (m = b*512 + i)
__device__ float g_a[HID_ * M_];
__device__ float g_c[HID_ * M_];

// Packed fp32x2 ops (Blackwell fma/add f32x2: 2x fp32 throughput on fma pipe)
__device__ __forceinline__ float2 ffma2(float2 a, float2 b, float2 c) {
    union F2U { float2 f; unsigned long long u; };
    F2U A, Bv, C, D;
    A.f = a; Bv.f = b; C.f = c;
    asm("fma.rn.f32x2 %0, %1, %2, %3;"
        : "=l"(D.u) : "l"(A.u), "l"(Bv.u), "l"(C.u));
    return D.f;
}
__device__ __forceinline__ float2 fadd2(float2 a, float2 b) {
    union F2U { float2 f; unsigned long long u; };
    F2U A, Bv, D;
    A.f = a; Bv.f = b;
    asm("add.rn.f32x2 %0, %1, %2;"
        : "=l"(D.u) : "l"(A.u), "l"(Bv.u));
    return D.f;
}

// ---------------------------------------------------------------------------
// Kernel 1: FUSED dual GEMM. Each block computes BOTH a and c tiles for one
// (m0,n0): 64m x 64n x 2 halves. Grid = 32 x 4 = 128 blocks = one clean wave.
// 512 threads, per thread 2m x 4n x 2 halves. BK = 32.
// Epilogue stores TRANSPOSED (d-major) into g_a / g_c.
// ---------------------------------------------------------------------------
#define GBK 32

__global__ void __launch_bounds__(512, 1)
gemm_kernel(const float* __restrict__ emb, const float* __restrict__ W1,
            const float* __restrict__ b1)
{
    const int m0 = blockIdx.y * 64;
    const int n0 = blockIdx.x * 64;

    __shared__ float As[GBK][66];   // emb tile, k-major (pad 66: conflict-free)
    __shared__ float Ba[GBK][68];   // Wa tile  (pad 68: float4-aligned)
    __shared__ float Bb[GBK][68];   // Wb tile

    const int t  = threadIdx.x;     // 512
    const int tx = t & 15;          // n: 4 cols each
    const int ty = t >> 4;          // m: 2 rows each (0..31)

    // fill-index precompute
    const int lr = t >> 3;          // emb row 0..63
    const int lq = (t & 7) * 4;     // emb k-offset (float4)
    const int wi = t & 255;
    const int wk = wi >> 4;         // W k-row 0..15 (and +16)
    const int wn = (wi & 15) * 4;   // W n-offset
    const float* __restrict__ Wsrc = W1 + (t < 256 ? 0 : H_ * HID_);

    float2 accA[2][2], accC[2][2];
    #pragma unroll
    for (int mi = 0; mi < 2; mi++)
        #pragma unroll
        for (int p = 0; p < 2; p++) {
            accA[mi][p] = make_float2(0.f, 0.f);
            accC[mi][p] = make_float2(0.f, 0.f);
        }

    for (int k0 = 0; k0 < H_; k0 += GBK) {
        // emb tile 64 x 32, transposed into As[k][m]
        {
            float4 v = *(const float4*)&emb[(m0 + lr) * H_ + k0 + lq];
            As[lq + 0][lr] = v.x; As[lq + 1][lr] = v.y;
            As[lq + 2][lr] = v.z; As[lq + 3][lr] = v.w;
        }
        // W tiles 32 x 64 (threads <256: Wa; >=256: Wb), 2 float4 each
        {
            float4 v0 = *(const float4*)&Wsrc[(k0 + wk) * HID_ + n0 + wn];
            float4 v1 = *(const float4*)&Wsrc[(k0 + wk + 16) * HID_ + n0 + wn];
            if (t < 256) {
                *(float4*)&Ba[wk][wn] = v0; *(float4*)&Ba[wk + 16][wn] = v1;
            } else {
                *(float4*)&Bb[wk][wn] = v0; *(float4*)&Bb[wk + 16][wn] = v1;
            }
        }
        __syncthreads();

        #pragma unroll
        for (int k = 0; k < GBK; k++) {
            const float2 av = *(const float2*)&As[k][ty * 2];
            const float4 ba = *(const float4*)&Ba[k][tx * 4];
            const float4 bb = *(const float4*)&Bb[k][tx * 4];
            const float2 ba01 = make_float2(ba.x, ba.y);
            const float2 ba23 = make_float2(ba.z, ba.w);
            const float2 bb01 = make_float2(bb.x, bb.y);
            const float2 bb23 = make_float2(bb.z, bb.w);
            const float am[2] = {av.x, av.y};
            #pragma unroll
            for (int mi = 0; mi < 2; mi++) {
                const float2 ap = make_float2(am[mi], am[mi]);
                accA[mi][0] = ffma2(ap, ba01, accA[mi][0]);
                accA[mi][1] = ffma2(ap, ba23, accA[mi][1]);
                accC[mi][0] = ffma2(ap, bb01, accC[mi][0]);
                accC[mi][1] = ffma2(ap, bb23, accC[mi][1]);
            }
        }
        __syncthreads();
    }

    // Epilogue: transposed store  g_a[n * M_ + m]  (+ b1 on the a-half)
    const float4 b1v = *(const float4*)&b1[n0 + tx * 4];
    const float b1a[4] = {b1v.x, b1v.y, b1v.z, b1v.w};
    const int m = m0 + ty * 2;
    #pragma unroll
    for (int p = 0; p < 2; p++) {
        #pragma unroll
        for (int e = 0; e < 2; e++) {
            const int jj = p * 2 + e;
            const int n = n0 + tx * 4 + jj;
            float2 oa, oc;
            if (e == 0) {
                oa = make_float2(accA[0][p].x + b1a[jj], accA[1][p].x + b1a[jj]);
                oc = make_float2(accC[0][p].x, accC[1][p].x);
            } else {
                oa = make_float2(accA[0][p].y + b1a[jj], accA[1][p].y + b1a[jj]);
                oc = make_float2(accC[0][p].y, accC[1][p].y);
            }
            *(float2*)&g_a[n * M_ + m] = oa;
            *(float2*)&g_c[n * M_ + m] = oc;
        }
    }
}

// ---------------------------------------------------------------------------
// Kernel 2: pairwise relu-dot. 32x32 tiles, 128 threads, 2i x 4j per thread.
// Grid = 16 x 16 x 4 = 1024 blocks (6.9/SM: ~1% imbalance, deep occupancy).
// g_a/g_c are d-major -> tile fills are plain coalesced float4 copies.
// Per 8 outputs*d: 4 ADD2 + 8 FMNMX(alu) + 4 FFMA2 + ~2.3 LDS.
// ---------------------------------------------------------------------------
#define PDK 32

__global__ void __launch_bounds__(128, 8)
pair_kernel(const float* __restrict__ W2, const float* __restrict__ b2,
            float* __restrict__ out)
{
    const int b  = blockIdx.z;
    const int i0 = blockIdx.y * 32;
    const int j0 = blockIdx.x * 32;
    const int ma = b * N_ + i0;     // column base into d-major g_a
    const int mc = b * N_ + j0;

    __shared__ float As[PDK][36];
    __shared__ float Cs[PDK][36];
    __shared__ float Ws[HID_];

    const int t  = threadIdx.x;     // 128
    const int tx = t & 7;           // j: 4 cols each
    const int ty = t >> 3;          // i: 2 rows each (0..15)

    Ws[t] = W2[t];
    Ws[t + 128] = W2[t + 128];

    const int fdk = t >> 2;         // fill d-row 0..31
    const int fs  = (t & 3) * 8;    // fill m-offset (two float4)

    float2 acc[2][2];
    #pragma unroll
    for (int mi = 0; mi < 2; mi++) {
        acc[mi][0] = make_float2(0.f, 0.f);
        acc[mi][1] = make_float2(0.f, 0.f);
    }

    for (int d0 = 0; d0 < HID_; d0 += PDK) {
        {
            const float* __restrict__ pa = &g_a[(d0 + fdk) * M_ + ma + fs];
            const float* __restrict__ pc = &g_c[(d0 + fdk) * M_ + mc + fs];
            float4 a0 = *(const float4*)(pa);
            float4 a1 = *(const float4*)(pa + 4);
            float4 c0 = *(const float4*)(pc);
            float4 c1 = *(const float4*)(pc + 4);
            *(float4*)&As[fdk][fs]     = a0;
            *(float4*)&As[fdk][fs + 4] = a1;
            *(float4*)&Cs[fdk][fs]     = c0;
            *(float4*)&Cs[fdk][fs + 4] = c1;
        }
        __syncthreads();

        #pragma unroll
        for (int g = 0; g < PDK / 4; g++) {
            const float4 wv = *(const float4*)&Ws[d0 + g * 4];
            const float wr[4] = {wv.x, wv.y, wv.z, wv.w};
            #pragma unroll
            for (int e = 0; e < 4; e++) {
                const int dk = g * 4 + e;
                const float2 wp = make_float2(wr[e], wr[e]);
                const float2 av = *(const float2*)&As[dk][ty * 2];
                const float4 cv = *(const float4*)&Cs[dk][tx * 4];
                const float2 c01 = make_float2(cv.x, cv.y);
                const float2 c23 = make_float2(cv.z, cv.w);
                const float am[2] = {av.x, av.y};
                #pragma unroll
                for (int mi = 0; mi < 2; mi++) {
                    const float2 ap = make_float2(am[mi], am[mi]);
                    float2 s0 = fadd2(ap, c01);
                    float2 s1 = fadd2(ap, c23);
                    s0.x = fmaxf(s0.x, 0.f); s0.y = fmaxf(s0.y, 0.f);
                    s1.x = fmaxf(s1.x, 0.f); s1.y = fmaxf(s1.y, 0.f);
                    acc[mi][0] = ffma2(s0, wp, acc[mi][0]);
                    acc[mi][1] = ffma2(s1, wp, acc[mi][1]);
                }
            }
        }
        __syncthreads();
    }

    const float bb = b2[0];
    const int j = j0 + tx * 4;
    #pragma unroll
    for (int mi = 0; mi < 2; mi++) {
        const int i = i0 + ty * 2 + mi;
        float4 o;
        o.x = acc[mi][0].x + bb;
        o.y = acc[mi][0].y + bb;
        o.z = acc[mi][1].x + bb;
        o.w = acc[mi][1].y + bb;
        *(float4*)&out[((size_t)b * N_ + i) * N_ + j] = o;
    }
}

// ---------------------------------------------------------------------------
extern "C" void kernel_launch(void* const* d_in, const int* in_sizes, int n_in,
                              void* d_out, int out_size)
{
    const float* emb = (const float*)d_in[0];
    const float* W1  = (const float*)d_in[1];
    const float* b1  = (const float*)d_in[2];
    const float* W2  = (const float*)d_in[3];
    const float* b2  = (const float*)d_in[4];
    float* out = (float*)d_out;

    dim3 ggrid(HID_ / 64, M_ / 64);          // 4 x 32 = 128 blocks
    gemm_kernel<<<ggrid, 512>>>(emb, W1, b1);

    dim3 pgrid(N_ / 32, N_ / 32, B_);        // 16 x 16 x 4 = 1024 blocks
    pair_kernel<<<pgrid, 128>>>(W2, b2, out);
}